// round 11
// baseline (speedup 1.0000x reference)
#include <cuda_runtime.h>
#include <math.h>

#define NB   1024
#define NTOK 256
#define NV   200
#define BT   32
#define KC   10
#define NCH  (NV / KC)   // 20 chunks
#define WROW 224         // padded W row (14 strips x 16)
#define XSTR 34          // XdT row stride in float2

typedef unsigned long long u64;

// ---------------- device scratch ----------------
__device__ float g_M[245];            // Mu[7][14] | Md[7][14] | Mp[7][7]
__device__ float g_udp[3][NB][NV];
__device__ float g_mean[3][NV];
__device__ float g_rstd[3][NV];

// ---------------- helpers ----------------
__device__ __forceinline__ float warp_sum(float v) {
#pragma unroll
    for (int o = 16; o; o >>= 1) v += __shfl_xor_sync(0xffffffffu, v, o);
    return v;
}
__device__ __forceinline__ float warp_max(float v) {
#pragma unroll
    for (int o = 16; o; o >>= 1) v = fmaxf(v, __shfl_xor_sync(0xffffffffu, v, o));
    return v;
}
__device__ __forceinline__ u64 ffma2(u64 a, u64 b, u64 c) {
    u64 d;
    asm("fma.rn.f32x2 %0, %1, %2, %3;" : "=l"(d) : "l"(a), "l"(b), "l"(c));
    return d;
}
union F2U { float2 f; u64 u; };
__device__ __forceinline__ float2 unpack2(u64 v) { F2U t; t.u = v; return t.f; }
__device__ __forceinline__ void cp16(unsigned dst, const void* src) {
    asm volatile("cp.async.cg.shared.global [%0], [%1], 16;" :: "r"(dst), "l"(src));
}
__device__ __forceinline__ void cp_commit() {
    asm volatile("cp.async.commit_group;");
}
template <int N>
__device__ __forceinline__ void cp_wait() {
    asm volatile("cp.async.wait_group %0;" :: "n"(N));
}

// ---------------- kernel 0: M = Wq @ Wk^T (once) ----------------
__global__ void k_pre(const float* __restrict__ upWq, const float* __restrict__ upWk,
                      const float* __restrict__ dnWq, const float* __restrict__ dnWk,
                      const float* __restrict__ pvWq, const float* __restrict__ pvWk) {
    int t = threadIdx.x;
    if (t >= 245) return;
    const float *Wq, *Wk; int j, f;
    if (t < 98)       { Wq = upWq; Wk = upWk; j = t / 14;        f = t % 14; }
    else if (t < 196) { Wq = dnWq; Wk = dnWk; j = (t - 98) / 14; f = (t - 98) % 14; }
    else              { Wq = pvWq; Wk = pvWk; j = (t - 196) / 7; f = (t - 196) % 7; }
    const float4* q4 = (const float4*)(Wq + j * NV);
    const float4* k4 = (const float4*)(Wk + f * NV);
    float s = 0.f;
#pragma unroll 5
    for (int v = 0; v < NV / 4; v++) {
        float4 qa = q4[v], ka = k4[v];
        s += qa.x * ka.x + qa.y * ka.y + qa.z * ka.z + qa.w * ka.w;
    }
    g_M[t] = s;
}

// ---------------- kernel 1: attention, block-per-batch ----------------
__global__ __launch_bounds__(256) void k_attn(
    const float* __restrict__ merged, const float* __restrict__ a,
    const float* __restrict__ upWv, const float* __restrict__ dnWv,
    const float* __restrict__ pvWv, float* __restrict__ out)
{
    __shared__ float feat[NTOK * 15];
    __shared__ float sM[245];
    __shared__ float sqk[35];
    __shared__ float wred[8][6];
    __shared__ float wpart[8][38];
    __shared__ float sred[38];

    int b = blockIdx.x, t = threadIdx.x;
    int wid = t >> 5, lane = t & 31;

    const float4* src4 = (const float4*)(merged + (size_t)b * NTOK * 15);
    float4* feat4 = (float4*)feat;
#pragma unroll
    for (int i = 0; i < 4; i++) {
        int idx = t + 256 * i;
        if (idx < 960) feat4[idx] = src4[idx];
    }
    if (b < 4) out[b * 256 + t] = 0.f;
    if (t < 245) sM[t] = g_M[t];
    float a_b = a[b];
    __syncthreads();

    float subj_id = feat[0], subj_loc = feat[2];
    if (t < 35) {
        float ego[7];
        ego[0] = 0.f; ego[1] = feat[1]; ego[2] = feat[2]; ego[3] = feat[3];
        ego[4] = feat[4]; ego[5] = feat[5]; ego[6] = a_b;
        float s = 0.f;
        if (t < 14) {
#pragma unroll
            for (int j = 0; j < 7; j++) s += ego[j] * sM[j * 14 + t];
        } else if (t < 28) {
            int f = t - 14;
#pragma unroll
            for (int j = 0; j < 7; j++) s += ego[j] * sM[98 + j * 14 + f];
        } else {
            int f = t - 28;
#pragma unroll
            for (int j = 0; j < 7; j++) s += ego[j] * sM[196 + j * 7 + f];
        }
        sqk[t] = s;
    }
    __syncthreads();

    float f[15];
#pragma unroll
    for (int q = 0; q < 15; q++) f[q] = feat[t * 15 + q];
    f[0] -= subj_id; f[7] -= subj_id;
    if (t == 0) f[6] = a_b;

    float s1 = 0.f, s2 = 0.f, s3 = 0.f;
#pragma unroll
    for (int q = 0; q < 14; q++) { s1 = fmaf(f[q], sqk[q], s1); s2 = fmaf(f[q], sqk[14 + q], s2); }
#pragma unroll
    for (int q = 0; q < 7; q++)  s3 = fmaf(f[q], sqk[28 + q], s3);

    const float scale = 0.07071067811865475f;
    bool fl1  = (f[14] == 1.0f);
    bool m_up = (f[2] < subj_loc) && fl1;
    bool m_dn = (f[2] > subj_loc) && fl1;
    bool m_pv = (f[14] == 0.0f);
    float su = m_up ? s1 * scale : -1e9f;
    float sd = m_dn ? s2 * scale : -1e9f;
    float sp = m_pv ? s3 * scale : -1e9f;

    float mu = warp_max(su), md = warp_max(sd), mp = warp_max(sp);
    float cu = warp_sum(m_up ? 1.f : 0.f);
    float cd = warp_sum(m_dn ? 1.f : 0.f);
    float cp = warp_sum(m_pv ? 1.f : 0.f);
    if (lane == 0) {
        wred[wid][0] = mu; wred[wid][1] = md; wred[wid][2] = mp;
        wred[wid][3] = cu; wred[wid][4] = cd; wred[wid][5] = cp;
    }
    __syncthreads();
    float BU = wred[0][0], BD = wred[0][1], BP = wred[0][2];
    float CU = wred[0][3], CD = wred[0][4], CP = wred[0][5];
#pragma unroll
    for (int w = 1; w < 8; w++) {
        BU = fmaxf(BU, wred[w][0]); BD = fmaxf(BD, wred[w][1]); BP = fmaxf(BP, wred[w][2]);
        CU += wred[w][3]; CD += wred[w][4]; CP += wred[w][5];
    }
    float eu = __expf(su - BU), ed = __expf(sd - BD), ep = __expf(sp - BP);

    float vals[38];
    vals[0] = eu; vals[1] = ed; vals[2] = ep;
#pragma unroll
    for (int q = 0; q < 14; q++) { vals[3 + q] = eu * f[q]; vals[17 + q] = ed * f[q]; }
#pragma unroll
    for (int q = 0; q < 7; q++)  vals[31 + q] = ep * f[q];
#pragma unroll
    for (int i = 0; i < 38; i++) {
        float v = warp_sum(vals[i]);
        if (lane == 0) wpart[wid][i] = v;
    }
    __syncthreads();
    if (t < 38) {
        float s = 0.f;
#pragma unroll
        for (int w = 0; w < 8; w++) s += wpart[w][t];
        sred[t] = s;
    }
    __syncthreads();

    if (t < NV) {
        float iSu = (CU > 0.5f) ? 1.f / sred[0] : 0.f;
        float iSd = (CD > 0.5f) ? 1.f / sred[1] : 0.f;
        float iSp = (CP > 0.5f) ? 1.f / sred[2] : 0.f;
        float ou = 0.f, od = 0.f, op = 0.f;
#pragma unroll
        for (int q = 0; q < 14; q++) {
            ou = fmaf(sred[3 + q],  __ldg(&upWv[q * NV + t]), ou);
            od = fmaf(sred[17 + q], __ldg(&dnWv[q * NV + t]), od);
        }
#pragma unroll
        for (int q = 0; q < 7; q++)
            op = fmaf(sred[31 + q], __ldg(&pvWv[q * NV + t]), op);
        g_udp[0][b][t] = ou * iSu;
        g_udp[1][b][t] = od * iSd;
        g_udp[2][b][t] = op * iSp;
    }
}

// ---------------- kernel 2: batch-norm stats (fp32, tree reduce) ----------------
__global__ void k_stats() {
    int k  = blockIdx.y;
    int vx = threadIdx.x;
    int by = threadIdx.y;
    int v  = blockIdx.x * 32 + vx;
    float s = 0.f, s2 = 0.f;
    if (v < NV) {
#pragma unroll 4
        for (int j = 0; j < 32; j++) {
            float x = g_udp[k][by + 32 * j][v];
            s += x;
            s2 = fmaf(x, x, s2);
        }
    }
    __shared__ float ss[32][33], ss2[32][33];
    ss[by][vx]  = s;
    ss2[by][vx] = s2;
    __syncthreads();
#pragma unroll
    for (int off = 16; off; off >>= 1) {
        if (by < off) {
            ss[by][vx]  += ss[by + off][vx];
            ss2[by][vx] += ss2[by + off][vx];
        }
        __syncthreads();
    }
    if (by == 0 && v < NV) {
        float mean = ss[0][vx] * (1.f / NB);
        float var  = ss2[0][vx] * (1.f / NB) - mean * mean;
        g_mean[k][v] = mean;
        g_rstd[k][v] = rsqrtf(var + 1e-5f);
    }
}

// ---------------- kernel 3: 200x200 GEMMs — 512 thr, operand-shared, 4x4 tile ----------------
// 16 warps; warp w (w<14) owns output strip [16w, 16w+16).
// Lane: og = lane&3 -> 4 outputs (o0 = 16w + og*4), bg = lane>>2 -> 4 batches (bg*4..+3).
// Per k per thread: 1 W-LDS.128 (64B unique/warp) + 2 X-LDS.128 + 8 FFMA2.
__global__ __launch_bounds__(512) void k_mlp(const float* __restrict__ merged,
                                             const float* __restrict__ a,
                                             const float* __restrict__ tW1,
                                             const float* __restrict__ tb1,
                                             const float* __restrict__ tW2,
                                             const float* __restrict__ tb2,
                                             const float* __restrict__ eW1,
                                             const float* __restrict__ eb1,
                                             const float* __restrict__ eW2,
                                             const float* __restrict__ eb2,
                                             const float* __restrict__ eW3,
                                             const float* __restrict__ eb3,
                                             const float* __restrict__ gamma,
                                             const float* __restrict__ beta,
                                             float* __restrict__ out) {
    int unit = blockIdx.y;        // 0..2 heads, 3 = ego net
    int b0   = blockIdx.x * BT;
    int t    = threadIdx.x;
    int wid  = t >> 5;            // 0..15 = output strip (14 active)
    int lane = t & 31;
    int og   = lane & 3;          // output group within warp
    int bg   = lane >> 2;         // batch group within warp (0..7)
    bool act = wid < 14;

    __align__(16) __shared__ float2 XdT[NV * XSTR + 2];   // [k][b] dup, 54,464 B
    __align__(16) __shared__ float  Wbuf[3][KC][WROW];    // 3 x 8,960 B

    // ---- build XdT (transposed, duplicated) ----
    if (unit < 3) {
        for (int i = t; i < BT * NV; i += 512) {
            int bb = i / NV, v = i - bb * NV;          // coalesced read along v
            float x = g_udp[unit][b0 + bb][v];
            x = gamma[v] * (x - g_mean[unit][v]) * g_rstd[unit][v] + beta[v];
            XdT[v * XSTR + bb] = make_float2(x, x);
        }
    } else {
        int half = t >> 8;            // 0 or 1
        int tt   = t & 255;
        if (tt < NV) {
            float w0 = eW1[tt], w1 = eW1[NV + tt], w2 = eW1[2 * NV + tt], w3 = eW1[3 * NV + tt];
            float bb1 = eb1[tt];
            for (int bb = half * 16; bb < half * 16 + 16; bb++) {
                const float* mr = merged + (size_t)(b0 + bb) * NTOK * 15;
                float h = fmaxf(mr[3] * w0 + mr[4] * w1 + mr[5] * w2 + a[b0 + bb] * w3 + bb1, 0.f);
                XdT[tt * XSTR + bb] = make_float2(h, h);
            }
        }
    }
    // zero W padding cols 200..223 in all 3 buffers
    for (int i = t; i < 3 * KC * (WROW - NV); i += 512) {
        int buf = i / (KC * (WROW - NV));
        int r   = i % (KC * (WROW - NV));
        int kc  = r / (WROW - NV), c = r % (WROW - NV);
        Wbuf[buf][kc][NV + c] = 0.f;
    }

    const float* Wg   = (unit < 3) ? tW1 + (size_t)unit * NV * NV : eW2;
    const float* bias = (unit < 3) ? tb1 + unit * NV : eb2;

    // stage chunks 0 and 1
#pragma unroll
    for (int pc = 0; pc < 2; pc++) {
        unsigned sb = (unsigned)__cvta_generic_to_shared(&Wbuf[pc][0][0]);
        const float* gsrc = Wg + (size_t)pc * KC * NV;
        for (int i = t; i < KC * (NV / 4); i += 512) {
            int kc = i / (NV / 4), c4 = i % (NV / 4);
            cp16(sb + (kc * WROW + c4 * 4) * 4, gsrc + kc * NV + c4 * 4);
        }
        cp_commit();
    }

    int o0 = wid * 16 + og * 4;
    u64 acc[4][2];
    {
        float b01x = 0.f, b01y = 0.f, b23x = 0.f, b23y = 0.f;
        if (act) {
            b01x = (o0 + 0 < NV) ? bias[o0 + 0] : 0.f;
            b01y = (o0 + 1 < NV) ? bias[o0 + 1] : 0.f;
            b23x = (o0 + 2 < NV) ? bias[o0 + 2] : 0.f;
            b23y = (o0 + 3 < NV) ? bias[o0 + 3] : 0.f;
        }
        F2U u0; u0.f = make_float2(b01x, b01y);
        F2U u1; u1.f = make_float2(b23x, b23y);
#pragma unroll
        for (int i = 0; i < 4; i++) { acc[i][0] = u0.u; acc[i][1] = u1.u; }
    }

    for (int c = 0; c < NCH; c++) {
        if (c + 2 < NCH) {
            unsigned sb = (unsigned)__cvta_generic_to_shared(&Wbuf[(c + 2) % 3][0][0]);
            const float* gsrc = Wg + (size_t)(c + 2) * KC * NV;
            for (int i = t; i < KC * (NV / 4); i += 512) {
                int kc = i / (NV / 4), c4 = i % (NV / 4);
                cp16(sb + (kc * WROW + c4 * 4) * 4, gsrc + kc * NV + c4 * 4);
            }
            cp_commit();
            cp_wait<2>();
        } else if (c + 1 < NCH) {
            cp_wait<1>();
        } else {
            cp_wait<0>();
        }
        __syncthreads();
        if (act) {
            const float* Wb = &Wbuf[c % 3][0][0];
            int k0 = c * KC;
#pragma unroll
            for (int kc = 0; kc < KC; kc++) {
                ulonglong2 w = *(const ulonglong2*)(Wb + kc * WROW + o0);
                const float2* xrow = XdT + (size_t)(k0 + kc) * XSTR + bg * 4;
                ulonglong2 x01 = *(const ulonglong2*)(xrow + 0);
                ulonglong2 x23 = *(const ulonglong2*)(xrow + 2);
                acc[0][0] = ffma2(x01.x, w.x, acc[0][0]); acc[0][1] = ffma2(x01.x, w.y, acc[0][1]);
                acc[1][0] = ffma2(x01.y, w.x, acc[1][0]); acc[1][1] = ffma2(x01.y, w.y, acc[1][1]);
                acc[2][0] = ffma2(x23.x, w.x, acc[2][0]); acc[2][1] = ffma2(x23.x, w.y, acc[2][1]);
                acc[3][0] = ffma2(x23.y, w.x, acc[3][0]); acc[3][1] = ffma2(x23.y, w.y, acc[3][1]);
            }
        }
        __syncthreads();   // protect Wbuf[c%3] before restage at c+3
    }

    // ---- epilogue: activation, *W2, per-batch partials ----
    float p[4] = {0.f, 0.f, 0.f, 0.f};
    if (act) {
        float w2v[4];
#pragma unroll
        for (int j = 0; j < 4; j++) {
            int o = o0 + j;
            w2v[j] = (o < NV) ? ((unit < 3) ? tW2[unit * NV + o] : eW3[o]) : 0.f;
        }
#pragma unroll
        for (int i = 0; i < 4; i++) {
            float2 v01 = unpack2(acc[i][0]);
            float2 v23 = unpack2(acc[i][1]);
            float v[4] = {v01.x, v01.y, v23.x, v23.y};
            float s = 0.f;
#pragma unroll
            for (int j = 0; j < 4; j++) {
                float x = v[j];
                x = (unit < 3) ? (x > 0.f ? x : expm1f(x)) : fmaxf(x, 0.f);
                s = fmaf(x, w2v[j], s);
            }
            p[i] = s;
        }
    }
    __syncthreads();                       // done with XdT
    float* red = (float*)XdT;              // red[56][33]
    if (act) {
        int r = wid * 4 + og;              // 0..55
#pragma unroll
        for (int i = 0; i < 4; i++) red[r * 33 + bg * 4 + i] = p[i];
    }
    __syncthreads();
    if (t < BT) {
        float s = 0.f;
        for (int j = 0; j < 56; j++) s += red[j * 33 + t];
        float fb = (unit < 3) ? tb2[unit] : eb3[0];
        atomicAdd(&out[b0 + t], s + fb);
    }
}

// ---------------- launch ----------------
extern "C" void kernel_launch(void* const* d_in, const int* in_sizes, int n_in,
                              void* d_out, int out_size) {
    (void)in_sizes; (void)n_in; (void)out_size;
    const float* merged = (const float*)d_in[0];
    const float* a      = (const float*)d_in[1];
    const float* upWq   = (const float*)d_in[2];
    const float* upWk   = (const float*)d_in[3];
    const float* upWv   = (const float*)d_in[4];
    const float* dnWq   = (const float*)d_in[5];
    const float* dnWk   = (const float*)d_in[6];
    const float* dnWv   = (const float*)d_in[7];
    const float* pvWq   = (const float*)d_in[8];
    const float* pvWk   = (const float*)d_in[9];
    const float* pvWv   = (const float*)d_in[10];
    const float* tW1    = (const float*)d_in[11];
    const float* tb1    = (const float*)d_in[12];
    const float* tW2    = (const float*)d_in[13];
    const float* tb2    = (const float*)d_in[14];
    const float* eW1    = (const float*)d_in[15];
    const float* eb1    = (const float*)d_in[16];
    const float* eW2    = (const float*)d_in[17];
    const float* eb2    = (const float*)d_in[18];
    const float* eW3    = (const float*)d_in[19];
    const float* eb3    = (const float*)d_in[20];
    const float* gamma  = (const float*)d_in[21];
    const float* beta   = (const float*)d_in[22];
    float* out = (float*)d_out;

    k_pre<<<1, 256>>>(upWq, upWk, dnWq, dnWk, pvWq, pvWk);
    k_attn<<<NB, 256>>>(merged, a, upWv, dnWv, pvWv, out);
    k_stats<<<dim3(7, 3), dim3(32, 32)>>>();
    k_mlp<<<dim3(NB / BT, 4), 512>>>(merged, a, tW1, tb1, tW2, tb2,
                                     eW1, eb1, eW2, eb2, eW3, eb3,
                                     gamma, beta, out);
}

// round 13
// speedup vs baseline: 1.0406x; 1.0406x over previous
#include <cuda_runtime.h>
#include <cuda_bf16.h>
#include <math.h>
#include <stdint.h>

#define NB   1024
#define NTOK 256
#define NV   200

// ---- HMMA tile config ----
#define MT    128      // batches per block
#define NT    64       // outputs per block
#define KPAD  208      // padded K (13 x 16)
#define NKS   13
#define XSTR  210      // bf16 row stride (odd word count -> conflict-light)

// dynamic smem offsets (bytes)
#define SM_XH  0
#define SM_XL  (SM_XH + MT * XSTR * 2)        // 53,760 each
#define SM_WH  (SM_XL + MT * XSTR * 2)
#define SM_WL  (SM_WH + NT * XSTR * 2)        // 26,880 each
#define SM_RED (SM_WL + NT * XSTR * 2)
#define SM_TOT (SM_RED + MT * 2 * 4)          // 162,304 B

// ---------------- device scratch ----------------
__device__ float g_M[245];            // Mu[7][14] | Md[7][14] | Mp[7][7]
__device__ float g_udp[3][NB][NV];
__device__ float g_mean[3][NV];
__device__ float g_rstd[3][NV];

// ---------------- helpers ----------------
__device__ __forceinline__ float warp_sum(float v) {
#pragma unroll
    for (int o = 16; o; o >>= 1) v += __shfl_xor_sync(0xffffffffu, v, o);
    return v;
}
__device__ __forceinline__ float warp_max(float v) {
#pragma unroll
    for (int o = 16; o; o >>= 1) v = fmaxf(v, __shfl_xor_sync(0xffffffffu, v, o));
    return v;
}
__device__ __forceinline__ void mma16816(float* c, const uint32_t* a, const uint32_t* b) {
    asm volatile(
        "mma.sync.aligned.m16n8k16.row.col.f32.bf16.bf16.f32 "
        "{%0,%1,%2,%3}, {%4,%5,%6,%7}, {%8,%9}, {%0,%1,%2,%3};"
        : "+f"(c[0]), "+f"(c[1]), "+f"(c[2]), "+f"(c[3])
        : "r"(a[0]), "r"(a[1]), "r"(a[2]), "r"(a[3]), "r"(b[0]), "r"(b[1]));
}
__device__ __forceinline__ void split_bf16(float x, __nv_bfloat16& hi, __nv_bfloat16& lo) {
    hi = __float2bfloat16(x);
    lo = __float2bfloat16(x - __bfloat162float(hi));
}

// ---------------- kernel 0: M = Wq @ Wk^T (once) ----------------
__global__ void k_pre(const float* __restrict__ upWq, const float* __restrict__ upWk,
                      const float* __restrict__ dnWq, const float* __restrict__ dnWk,
                      const float* __restrict__ pvWq, const float* __restrict__ pvWk) {
    int t = threadIdx.x;
    if (t >= 245) return;
    const float *Wq, *Wk; int j, f;
    if (t < 98)       { Wq = upWq; Wk = upWk; j = t / 14;        f = t % 14; }
    else if (t < 196) { Wq = dnWq; Wk = dnWk; j = (t - 98) / 14; f = (t - 98) % 14; }
    else              { Wq = pvWq; Wk = pvWk; j = (t - 196) / 7; f = (t - 196) % 7; }
    const float4* q4 = (const float4*)(Wq + j * NV);
    const float4* k4 = (const float4*)(Wk + f * NV);
    float s = 0.f;
#pragma unroll 5
    for (int v = 0; v < NV / 4; v++) {
        float4 qa = q4[v], ka = k4[v];
        s += qa.x * ka.x + qa.y * ka.y + qa.z * ka.z + qa.w * ka.w;
    }
    g_M[t] = s;
}

// ---------------- kernel 1: attention, block-per-batch ----------------
__global__ __launch_bounds__(256) void k_attn(
    const float* __restrict__ merged, const float* __restrict__ a,
    const float* __restrict__ upWv, const float* __restrict__ dnWv,
    const float* __restrict__ pvWv, float* __restrict__ out)
{
    __shared__ float feat[NTOK * 15];
    __shared__ float sM[245];
    __shared__ float sqk[35];
    __shared__ float wred[8][6];
    __shared__ float wpart[8][38];
    __shared__ float sred[38];

    int b = blockIdx.x, t = threadIdx.x;
    int wid = t >> 5, lane = t & 31;

    const float4* src4 = (const float4*)(merged + (size_t)b * NTOK * 15);
    float4* feat4 = (float4*)feat;
#pragma unroll
    for (int i = 0; i < 4; i++) {
        int idx = t + 256 * i;
        if (idx < 960) feat4[idx] = src4[idx];
    }
    if (b < 4) out[b * 256 + t] = 0.f;
    if (t < 245) sM[t] = g_M[t];
    float a_b = a[b];
    __syncthreads();

    float subj_id = feat[0], subj_loc = feat[2];
    if (t < 35) {
        float ego[7];
        ego[0] = 0.f; ego[1] = feat[1]; ego[2] = feat[2]; ego[3] = feat[3];
        ego[4] = feat[4]; ego[5] = feat[5]; ego[6] = a_b;
        float s = 0.f;
        if (t < 14) {
#pragma unroll
            for (int j = 0; j < 7; j++) s += ego[j] * sM[j * 14 + t];
        } else if (t < 28) {
            int f = t - 14;
#pragma unroll
            for (int j = 0; j < 7; j++) s += ego[j] * sM[98 + j * 14 + f];
        } else {
            int f = t - 28;
#pragma unroll
            for (int j = 0; j < 7; j++) s += ego[j] * sM[196 + j * 7 + f];
        }
        sqk[t] = s;
    }
    __syncthreads();

    float f[15];
#pragma unroll
    for (int q = 0; q < 15; q++) f[q] = feat[t * 15 + q];
    f[0] -= subj_id; f[7] -= subj_id;
    if (t == 0) f[6] = a_b;

    float s1 = 0.f, s2 = 0.f, s3 = 0.f;
#pragma unroll
    for (int q = 0; q < 14; q++) { s1 = fmaf(f[q], sqk[q], s1); s2 = fmaf(f[q], sqk[14 + q], s2); }
#pragma unroll
    for (int q = 0; q < 7; q++)  s3 = fmaf(f[q], sqk[28 + q], s3);

    const float scale = 0.07071067811865475f;
    bool fl1  = (f[14] == 1.0f);
    bool m_up = (f[2] < subj_loc) && fl1;
    bool m_dn = (f[2] > subj_loc) && fl1;
    bool m_pv = (f[14] == 0.0f);
    float su = m_up ? s1 * scale : -1e9f;
    float sd = m_dn ? s2 * scale : -1e9f;
    float sp = m_pv ? s3 * scale : -1e9f;

    float mu = warp_max(su), md = warp_max(sd), mp = warp_max(sp);
    float cu = warp_sum(m_up ? 1.f : 0.f);
    float cd = warp_sum(m_dn ? 1.f : 0.f);
    float cp = warp_sum(m_pv ? 1.f : 0.f);
    if (lane == 0) {
        wred[wid][0] = mu; wred[wid][1] = md; wred[wid][2] = mp;
        wred[wid][3] = cu; wred[wid][4] = cd; wred[wid][5] = cp;
    }
    __syncthreads();
    float BU = wred[0][0], BD = wred[0][1], BP = wred[0][2];
    float CU = wred[0][3], CD = wred[0][4], CP = wred[0][5];
#pragma unroll
    for (int w = 1; w < 8; w++) {
        BU = fmaxf(BU, wred[w][0]); BD = fmaxf(BD, wred[w][1]); BP = fmaxf(BP, wred[w][2]);
        CU += wred[w][3]; CD += wred[w][4]; CP += wred[w][5];
    }
    float eu = __expf(su - BU), ed = __expf(sd - BD), ep = __expf(sp - BP);

    float vals[38];
    vals[0] = eu; vals[1] = ed; vals[2] = ep;
#pragma unroll
    for (int q = 0; q < 14; q++) { vals[3 + q] = eu * f[q]; vals[17 + q] = ed * f[q]; }
#pragma unroll
    for (int q = 0; q < 7; q++)  vals[31 + q] = ep * f[q];
#pragma unroll
    for (int i = 0; i < 38; i++) {
        float v = warp_sum(vals[i]);
        if (lane == 0) wpart[wid][i] = v;
    }
    __syncthreads();
    if (t < 38) {
        float s = 0.f;
#pragma unroll
        for (int w = 0; w < 8; w++) s += wpart[w][t];
        sred[t] = s;
    }
    __syncthreads();

    if (t < NV) {
        float iSu = (CU > 0.5f) ? 1.f / sred[0] : 0.f;
        float iSd = (CD > 0.5f) ? 1.f / sred[1] : 0.f;
        float iSp = (CP > 0.5f) ? 1.f / sred[2] : 0.f;
        float ou = 0.f, od = 0.f, op = 0.f;
#pragma unroll
        for (int q = 0; q < 14; q++) {
            ou = fmaf(sred[3 + q],  __ldg(&upWv[q * NV + t]), ou);
            od = fmaf(sred[17 + q], __ldg(&dnWv[q * NV + t]), od);
        }
#pragma unroll
        for (int q = 0; q < 7; q++)
            op = fmaf(sred[31 + q], __ldg(&pvWv[q * NV + t]), op);
        g_udp[0][b][t] = ou * iSu;
        g_udp[1][b][t] = od * iSd;
        g_udp[2][b][t] = op * iSp;
    }
}

// ---------------- kernel 2: batch-norm stats (fp32, tree reduce) ----------------
__global__ void k_stats() {
    int k  = blockIdx.y;
    int vx = threadIdx.x;
    int by = threadIdx.y;
    int v  = blockIdx.x * 32 + vx;
    float s = 0.f, s2 = 0.f;
    if (v < NV) {
#pragma unroll 4
        for (int j = 0; j < 32; j++) {
            float x = g_udp[k][by + 32 * j][v];
            s += x;
            s2 = fmaf(x, x, s2);
        }
    }
    __shared__ float ss[32][33], ss2[32][33];
    ss[by][vx]  = s;
    ss2[by][vx] = s2;
    __syncthreads();
#pragma unroll
    for (int off = 16; off; off >>= 1) {
        if (by < off) {
            ss[by][vx]  += ss[by + off][vx];
            ss2[by][vx] += ss2[by + off][vx];
        }
        __syncthreads();
    }
    if (by == 0 && v < NV) {
        float mean = ss[0][vx] * (1.f / NB);
        float var  = ss2[0][vx] * (1.f / NB) - mean * mean;
        g_mean[k][v] = mean;
        g_rstd[k][v] = rsqrtf(var + 1e-5f);
    }
}

// ---------------- kernel 3: HMMA bf16 split GEMM ----------------
// Block = 128 batches x 64 outputs x full K (pad 208). 8 warps: (4 M x 2 N) of 32x32.
// D = Xh*Wh + Xh*Wl + Xl*Wh via mma.sync.m16n8k16 (bf16 -> fp32).
__global__ __launch_bounds__(256) void k_mlp(const float* __restrict__ merged,
                                             const float* __restrict__ a,
                                             const float* __restrict__ tW1,
                                             const float* __restrict__ tb1,
                                             const float* __restrict__ tW2,
                                             const float* __restrict__ tb2,
                                             const float* __restrict__ eW1,
                                             const float* __restrict__ eb1,
                                             const float* __restrict__ eW2,
                                             const float* __restrict__ eb2,
                                             const float* __restrict__ eW3,
                                             const float* __restrict__ eb3,
                                             const float* __restrict__ gamma,
                                             const float* __restrict__ beta,
                                             float* __restrict__ out) {
    extern __shared__ char smem[];
    __nv_bfloat16* Xh = (__nv_bfloat16*)(smem + SM_XH);
    __nv_bfloat16* Xl = (__nv_bfloat16*)(smem + SM_XL);
    __nv_bfloat16* Wh = (__nv_bfloat16*)(smem + SM_WH);
    __nv_bfloat16* Wl = (__nv_bfloat16*)(smem + SM_WL);
    float*        red = (float*)(smem + SM_RED);          // [128][2]

    int t     = threadIdx.x;
    int wid   = t >> 5, lane = t & 31;
    int g     = lane >> 2;            // 0..7
    int la    = lane & 3;             // 0..3
    int wm    = wid >> 1;             // 0..3 : batch strip [wm*32, +32)
    int wn    = wid & 1;              // 0..1 : output strip [wn*32, +32)
    int b0    = blockIdx.x * MT;
    int oBase = blockIdx.y * NT;
    int unit  = blockIdx.z;

    // ---- stage X hi/lo (float4 over v) ----
    if (unit < 3) {
        for (int i = t; i < MT * (KPAD / 4); i += 256) {
            int bb = i / (KPAD / 4), v4 = (i - bb * (KPAD / 4)) * 4;
            float x0 = 0.f, x1 = 0.f, x2 = 0.f, x3 = 0.f;
            if (v4 < NV) {
                float4 xv = *(const float4*)&g_udp[unit][b0 + bb][v4];
                float4 gm = *(const float4*)&gamma[v4];
                float4 mn = *(const float4*)&g_mean[unit][v4];
                float4 rs = *(const float4*)&g_rstd[unit][v4];
                float4 bt = *(const float4*)&beta[v4];
                x0 = gm.x * (xv.x - mn.x) * rs.x + bt.x;
                x1 = gm.y * (xv.y - mn.y) * rs.y + bt.y;
                x2 = gm.z * (xv.z - mn.z) * rs.z + bt.z;
                x3 = gm.w * (xv.w - mn.w) * rs.w + bt.w;
            }
            __nv_bfloat16 h, l;
            int base = bb * XSTR + v4;
            split_bf16(x0, h, l); Xh[base + 0] = h; Xl[base + 0] = l;
            split_bf16(x1, h, l); Xh[base + 1] = h; Xl[base + 1] = l;
            split_bf16(x2, h, l); Xh[base + 2] = h; Xl[base + 2] = l;
            split_bf16(x3, h, l); Xh[base + 3] = h; Xl[base + 3] = l;
        }
    } else {
        if (t < NV) {
            float w0 = eW1[t], w1 = eW1[NV + t], w2 = eW1[2 * NV + t], w3 = eW1[3 * NV + t];
            float bb1 = eb1[t];
            for (int bb = 0; bb < MT; bb++) {
                const float* mr = merged + (size_t)(b0 + bb) * NTOK * 15;
                float h = fmaxf(mr[3] * w0 + mr[4] * w1 + mr[5] * w2 + a[b0 + bb] * w3 + bb1, 0.f);
                __nv_bfloat16 hh, ll;
                split_bf16(h, hh, ll);
                Xh[bb * XSTR + t] = hh;
                Xl[bb * XSTR + t] = ll;
            }
        }
        // zero pad k = 200..207
        for (int i = t; i < MT * 8; i += 256) {
            int bb = i >> 3, v = NV + (i & 7);
            Xh[bb * XSTR + v] = __float2bfloat16(0.f);
            Xl[bb * XSTR + v] = __float2bfloat16(0.f);
        }
    }

    // ---- stage W^T hi/lo: Ws[o][k] = Wg[k][oBase+o] ----
    {
        const float* Wg = (unit < 3) ? tW1 + (size_t)unit * NV * NV : eW2;
        for (int i = t; i < KPAD * NT; i += 256) {
            int v = i / NT, o = i - v * NT;      // coalesced over o
            int oo = oBase + o;
            float wv = (v < NV && oo < NV) ? Wg[(size_t)v * NV + oo] : 0.f;
            __nv_bfloat16 h, l;
            split_bf16(wv, h, l);
            Wh[o * XSTR + v] = h;
            Wl[o * XSTR + v] = l;
        }
    }
    __syncthreads();

    // ---- HMMA main loop ----
    float c[2][4][4];
#pragma unroll
    for (int mi = 0; mi < 2; mi++)
#pragma unroll
        for (int ni = 0; ni < 4; ni++)
#pragma unroll
            for (int j = 0; j < 4; j++) c[mi][ni][j] = 0.f;

#pragma unroll
    for (int s = 0; s < NKS; s++) {
        int kb = s * 16;
        int k0 = kb + la * 2;
        uint32_t ah[2][4], al[2][4];
#pragma unroll
        for (int mi = 0; mi < 2; mi++) {
            int r = wm * 32 + mi * 16 + g;
            ah[mi][0] = *(const uint32_t*)&Xh[r * XSTR + k0];
            ah[mi][1] = *(const uint32_t*)&Xh[(r + 8) * XSTR + k0];
            ah[mi][2] = *(const uint32_t*)&Xh[r * XSTR + k0 + 8];
            ah[mi][3] = *(const uint32_t*)&Xh[(r + 8) * XSTR + k0 + 8];
            al[mi][0] = *(const uint32_t*)&Xl[r * XSTR + k0];
            al[mi][1] = *(const uint32_t*)&Xl[(r + 8) * XSTR + k0];
            al[mi][2] = *(const uint32_t*)&Xl[r * XSTR + k0 + 8];
            al[mi][3] = *(const uint32_t*)&Xl[(r + 8) * XSTR + k0 + 8];
        }
#pragma unroll
        for (int ni = 0; ni < 4; ni++) {
            int n = wn * 32 + ni * 8 + g;
            uint32_t bh[2], bl[2];
            bh[0] = *(const uint32_t*)&Wh[n * XSTR + k0];
            bh[1] = *(const uint32_t*)&Wh[n * XSTR + k0 + 8];
            bl[0] = *(const uint32_t*)&Wl[n * XSTR + k0];
            bl[1] = *(const uint32_t*)&Wl[n * XSTR + k0 + 8];
#pragma unroll
            for (int mi = 0; mi < 2; mi++) {
                mma16816(c[mi][ni], ah[mi], bh);
                mma16816(c[mi][ni], ah[mi], bl);
                mma16816(c[mi][ni], al[mi], bh);
            }
        }
    }

    // ---- epilogue: bias + act + *W2, quad reduce, smem, atomicAdd ----
    const float* b1 = (unit < 3) ? tb1 + unit * NV : eb2;
    const float* w2 = (unit < 3) ? tW2 + unit * NV : eW3;

    float srow[2][2];   // [mi][half]
#pragma unroll
    for (int mi = 0; mi < 2; mi++) {
        srow[mi][0] = 0.f; srow[mi][1] = 0.f;
#pragma unroll
        for (int ni = 0; ni < 4; ni++) {
#pragma unroll
            for (int j = 0; j < 2; j++) {
                int oo = oBase + wn * 32 + ni * 8 + la * 2 + j;
                if (oo < NV) {
                    float bias = b1[oo], wv = w2[oo];
                    float v0 = c[mi][ni][j] + bias;        // row g
                    float v1 = c[mi][ni][2 + j] + bias;    // row g+8
                    if (unit < 3) {
                        v0 = v0 > 0.f ? v0 : expm1f(v0);
                        v1 = v1 > 0.f ? v1 : expm1f(v1);
                    } else {
                        v0 = fmaxf(v0, 0.f);
                        v1 = fmaxf(v1, 0.f);
                    }
                    srow[mi][0] = fmaf(v0, wv, srow[mi][0]);
                    srow[mi][1] = fmaf(v1, wv, srow[mi][1]);
                }
            }
        }
        // reduce across the 4 lanes of the quad (same rows, disjoint cols)
#pragma unroll
        for (int off = 1; off <= 2; off <<= 1) {
            srow[mi][0] += __shfl_xor_sync(0xffffffffu, srow[mi][0], off);
            srow[mi][1] += __shfl_xor_sync(0xffffffffu, srow[mi][1], off);
        }
    }
    if (la == 0) {
#pragma unroll
        for (int mi = 0; mi < 2; mi++) {
            int r0 = wm * 32 + mi * 16 + g;
            red[r0 * 2 + wn]       = srow[mi][0];
            red[(r0 + 8) * 2 + wn] = srow[mi][1];
        }
    }
    __syncthreads();
    if (t < MT) {
        float s = red[t * 2 + 0] + red[t * 2 + 1];
        if (blockIdx.y == 0) s += (unit < 3) ? tb2[unit] : eb3[0];
        atomicAdd(&out[b0 + t], s);
    }
}

// ---------------- launch ----------------
extern "C" void kernel_launch(void* const* d_in, const int* in_sizes, int n_in,
                              void* d_out, int out_size) {
    (void)in_sizes; (void)n_in; (void)out_size;
    const float* merged = (const float*)d_in[0];
    const float* a      = (const float*)d_in[1];
    const float* upWq   = (const float*)d_in[2];
    const float* upWk   = (const float*)d_in[3];
    const float* upWv   = (const float*)d_in[4];
    const float* dnWq   = (const float*)d_in[5];
    const float* dnWk   = (const float*)d_in[6];
    const float* dnWv   = (const float*)d_in[7];
    const float* pvWq   = (const float*)d_in[8];
    const float* pvWk   = (const float*)d_in[9];
    const float* pvWv   = (const float*)d_in[10];
    const float* tW1    = (const float*)d_in[11];
    const float* tb1    = (const float*)d_in[12];
    const float* tW2    = (const float*)d_in[13];
    const float* tb2    = (const float*)d_in[14];
    const float* eW1    = (const float*)d_in[15];
    const float* eb1    = (const float*)d_in[16];
    const float* eW2    = (const float*)d_in[17];
    const float* eb2    = (const float*)d_in[18];
    const float* eW3    = (const float*)d_in[19];
    const float* eb3    = (const float*)d_in[20];
    const float* gamma  = (const float*)d_in[21];
    const float* beta   = (const float*)d_in[22];
    float* out = (float*)d_out;

    static bool attr_set = false;
    if (!attr_set) {
        cudaFuncSetAttribute(k_mlp, cudaFuncAttributeMaxDynamicSharedMemorySize, SM_TOT);
        attr_set = true;
    }

    k_pre<<<1, 256>>>(upWq, upWk, dnWq, dnWk, pvWq, pvWk);
    k_attn<<<NB, 256>>>(merged, a, upWv, dnWv, pvWv, out);
    k_stats<<<dim3(7, 3), dim3(32, 32)>>>();
    k_mlp<<<dim3(NB / MT, 4, 4), 256, SM_TOT>>>(merged, a, tW1, tb1, tW2, tb2,
                                                eW1, eb1, eW2, eb2, eW3, eb3,
                                                gamma, beta, out);
}

// round 14
// speedup vs baseline: 1.1381x; 1.0937x over previous
#include <cuda_runtime.h>
#include <cuda_bf16.h>
#include <math.h>
#include <stdint.h>

#define NB   1024
#define NTOK 256
#define NV   200

// ---- HMMA tile config ----
#define MT    64       // batches per block
#define NT    64       // outputs per block
#define KPAD  208      // padded K (13 x 16)
#define NKS   13
#define XSTR  210      // bf16 row stride (even for 4B pair stores, 105-word half-stride)

// dynamic smem offsets (bytes)
#define SM_XH  0
#define SM_XL  (SM_XH + MT * XSTR * 2)        // 26,880 each
#define SM_WH  (SM_XL + MT * XSTR * 2)
#define SM_WL  (SM_WH + NT * XSTR * 2)
#define SM_RED (SM_WL + NT * XSTR * 2)
#define SM_TOT (SM_RED + MT * 4 * 4)          // 108,544 B -> 2 blocks/SM

// ---------------- device scratch ----------------
__device__ float g_M[245];            // Mu[7][14] | Md[7][14] | Mp[7][7]
__device__ float g_udp[3][NB][NV];
__device__ float g_mean[3][NV];
__device__ float g_rstd[3][NV];

// ---------------- helpers ----------------
__device__ __forceinline__ float warp_sum(float v) {
#pragma unroll
    for (int o = 16; o; o >>= 1) v += __shfl_xor_sync(0xffffffffu, v, o);
    return v;
}
__device__ __forceinline__ float warp_max(float v) {
#pragma unroll
    for (int o = 16; o; o >>= 1) v = fmaxf(v, __shfl_xor_sync(0xffffffffu, v, o));
    return v;
}
__device__ __forceinline__ void mma16816(float* c, const uint32_t* a, const uint32_t* b) {
    asm volatile(
        "mma.sync.aligned.m16n8k16.row.col.f32.bf16.bf16.f32 "
        "{%0,%1,%2,%3}, {%4,%5,%6,%7}, {%8,%9}, {%0,%1,%2,%3};"
        : "+f"(c[0]), "+f"(c[1]), "+f"(c[2]), "+f"(c[3])
        : "r"(a[0]), "r"(a[1]), "r"(a[2]), "r"(a[3]), "r"(b[0]), "r"(b[1]));
}
__device__ __forceinline__ uint32_t pack_bf16x2(float x, float y) {
    __nv_bfloat162 p = __floats2bfloat162_rn(x, y);
    return *(uint32_t*)&p;
}
// hi/lo split of two floats -> packed hi pair + lo pair
__device__ __forceinline__ void split2(float x0, float x1, uint32_t& hi, uint32_t& lo) {
    __nv_bfloat16 h0 = __float2bfloat16(x0);
    __nv_bfloat16 h1 = __float2bfloat16(x1);
    float r0 = x0 - __bfloat162float(h0);
    float r1 = x1 - __bfloat162float(h1);
    __nv_bfloat162 hp; hp.x = h0; hp.y = h1;
    hi = *(uint32_t*)&hp;
    lo = pack_bf16x2(r0, r1);
}

// ---------------- kernel 0: M = Wq @ Wk^T (once) ----------------
__global__ void k_pre(const float* __restrict__ upWq, const float* __restrict__ upWk,
                      const float* __restrict__ dnWq, const float* __restrict__ dnWk,
                      const float* __restrict__ pvWq, const float* __restrict__ pvWk) {
    int t = threadIdx.x;
    if (t >= 245) return;
    const float *Wq, *Wk; int j, f;
    if (t < 98)       { Wq = upWq; Wk = upWk; j = t / 14;        f = t % 14; }
    else if (t < 196) { Wq = dnWq; Wk = dnWk; j = (t - 98) / 14; f = (t - 98) % 14; }
    else              { Wq = pvWq; Wk = pvWk; j = (t - 196) / 7; f = (t - 196) % 7; }
    const float4* q4 = (const float4*)(Wq + j * NV);
    const float4* k4 = (const float4*)(Wk + f * NV);
    float s = 0.f;
#pragma unroll 5
    for (int v = 0; v < NV / 4; v++) {
        float4 qa = q4[v], ka = k4[v];
        s += qa.x * ka.x + qa.y * ka.y + qa.z * ka.z + qa.w * ka.w;
    }
    g_M[t] = s;
}

// ---------------- kernel 1: attention, block-per-batch ----------------
__global__ __launch_bounds__(256) void k_attn(
    const float* __restrict__ merged, const float* __restrict__ a,
    const float* __restrict__ upWv, const float* __restrict__ dnWv,
    const float* __restrict__ pvWv, float* __restrict__ out)
{
    __shared__ float feat[NTOK * 15];
    __shared__ float sM[245];
    __shared__ float sqk[35];
    __shared__ float wred[8][6];
    __shared__ float wpart[8][38];
    __shared__ float sred[38];

    int b = blockIdx.x, t = threadIdx.x;
    int wid = t >> 5, lane = t & 31;

    const float4* src4 = (const float4*)(merged + (size_t)b * NTOK * 15);
    float4* feat4 = (float4*)feat;
#pragma unroll
    for (int i = 0; i < 4; i++) {
        int idx = t + 256 * i;
        if (idx < 960) feat4[idx] = src4[idx];
    }
    if (b < 4) out[b * 256 + t] = 0.f;
    if (t < 245) sM[t] = g_M[t];
    float a_b = a[b];
    __syncthreads();

    float subj_id = feat[0], subj_loc = feat[2];
    if (t < 35) {
        float ego[7];
        ego[0] = 0.f; ego[1] = feat[1]; ego[2] = feat[2]; ego[3] = feat[3];
        ego[4] = feat[4]; ego[5] = feat[5]; ego[6] = a_b;
        float s = 0.f;
        if (t < 14) {
#pragma unroll
            for (int j = 0; j < 7; j++) s += ego[j] * sM[j * 14 + t];
        } else if (t < 28) {
            int f = t - 14;
#pragma unroll
            for (int j = 0; j < 7; j++) s += ego[j] * sM[98 + j * 14 + f];
        } else {
            int f = t - 28;
#pragma unroll
            for (int j = 0; j < 7; j++) s += ego[j] * sM[196 + j * 7 + f];
        }
        sqk[t] = s;
    }
    __syncthreads();

    float f[15];
#pragma unroll
    for (int q = 0; q < 15; q++) f[q] = feat[t * 15 + q];
    f[0] -= subj_id; f[7] -= subj_id;
    if (t == 0) f[6] = a_b;

    float s1 = 0.f, s2 = 0.f, s3 = 0.f;
#pragma unroll
    for (int q = 0; q < 14; q++) { s1 = fmaf(f[q], sqk[q], s1); s2 = fmaf(f[q], sqk[14 + q], s2); }
#pragma unroll
    for (int q = 0; q < 7; q++)  s3 = fmaf(f[q], sqk[28 + q], s3);

    const float scale = 0.07071067811865475f;
    bool fl1  = (f[14] == 1.0f);
    bool m_up = (f[2] < subj_loc) && fl1;
    bool m_dn = (f[2] > subj_loc) && fl1;
    bool m_pv = (f[14] == 0.0f);
    float su = m_up ? s1 * scale : -1e9f;
    float sd = m_dn ? s2 * scale : -1e9f;
    float sp = m_pv ? s3 * scale : -1e9f;

    float mu = warp_max(su), md = warp_max(sd), mp = warp_max(sp);
    float cu = warp_sum(m_up ? 1.f : 0.f);
    float cd = warp_sum(m_dn ? 1.f : 0.f);
    float cp = warp_sum(m_pv ? 1.f : 0.f);
    if (lane == 0) {
        wred[wid][0] = mu; wred[wid][1] = md; wred[wid][2] = mp;
        wred[wid][3] = cu; wred[wid][4] = cd; wred[wid][5] = cp;
    }
    __syncthreads();
    float BU = wred[0][0], BD = wred[0][1], BP = wred[0][2];
    float CU = wred[0][3], CD = wred[0][4], CP = wred[0][5];
#pragma unroll
    for (int w = 1; w < 8; w++) {
        BU = fmaxf(BU, wred[w][0]); BD = fmaxf(BD, wred[w][1]); BP = fmaxf(BP, wred[w][2]);
        CU += wred[w][3]; CD += wred[w][4]; CP += wred[w][5];
    }
    float eu = __expf(su - BU), ed = __expf(sd - BD), ep = __expf(sp - BP);

    float vals[38];
    vals[0] = eu; vals[1] = ed; vals[2] = ep;
#pragma unroll
    for (int q = 0; q < 14; q++) { vals[3 + q] = eu * f[q]; vals[17 + q] = ed * f[q]; }
#pragma unroll
    for (int q = 0; q < 7; q++)  vals[31 + q] = ep * f[q];
#pragma unroll
    for (int i = 0; i < 38; i++) {
        float v = warp_sum(vals[i]);
        if (lane == 0) wpart[wid][i] = v;
    }
    __syncthreads();
    if (t < 38) {
        float s = 0.f;
#pragma unroll
        for (int w = 0; w < 8; w++) s += wpart[w][t];
        sred[t] = s;
    }
    __syncthreads();

    if (t < NV) {
        float iSu = (CU > 0.5f) ? 1.f / sred[0] : 0.f;
        float iSd = (CD > 0.5f) ? 1.f / sred[1] : 0.f;
        float iSp = (CP > 0.5f) ? 1.f / sred[2] : 0.f;
        float ou = 0.f, od = 0.f, op = 0.f;
#pragma unroll
        for (int q = 0; q < 14; q++) {
            ou = fmaf(sred[3 + q],  __ldg(&upWv[q * NV + t]), ou);
            od = fmaf(sred[17 + q], __ldg(&dnWv[q * NV + t]), od);
        }
#pragma unroll
        for (int q = 0; q < 7; q++)
            op = fmaf(sred[31 + q], __ldg(&pvWv[q * NV + t]), op);
        g_udp[0][b][t] = ou * iSu;
        g_udp[1][b][t] = od * iSd;
        g_udp[2][b][t] = op * iSp;
    }
}

// ---------------- kernel 2: batch-norm stats (fp32, tree reduce) ----------------
__global__ void k_stats() {
    int k  = blockIdx.y;
    int vx = threadIdx.x;
    int by = threadIdx.y;
    int v  = blockIdx.x * 32 + vx;
    float s = 0.f, s2 = 0.f;
    if (v < NV) {
#pragma unroll 4
        for (int j = 0; j < 32; j++) {
            float x = g_udp[k][by + 32 * j][v];
            s += x;
            s2 = fmaf(x, x, s2);
        }
    }
    __shared__ float ss[32][33], ss2[32][33];
    ss[by][vx]  = s;
    ss2[by][vx] = s2;
    __syncthreads();
#pragma unroll
    for (int off = 16; off; off >>= 1) {
        if (by < off) {
            ss[by][vx]  += ss[by + off][vx];
            ss2[by][vx] += ss2[by + off][vx];
        }
        __syncthreads();
    }
    if (by == 0 && v < NV) {
        float mean = ss[0][vx] * (1.f / NB);
        float var  = ss2[0][vx] * (1.f / NB) - mean * mean;
        g_mean[k][v] = mean;
        g_rstd[k][v] = rsqrtf(var + 1e-5f);
    }
}

// ---------------- kernel 3: HMMA bf16 split GEMM (pass-reordered) ----------------
// Block = 64 batches x 64 outputs x full K. grid (16, 4, 4) = 256 blocks, 2/SM.
// 8 warps: wm = wid>>2 (2 M strips of 32), wn = wid&3 (4 N strips of 16).
// D = Xh*Wh (chh) + Xh*Wl + Xl*Wh (ccr), summed in epilogue.
__global__ __launch_bounds__(256) void k_mlp(const float* __restrict__ merged,
                                             const float* __restrict__ a,
                                             const float* __restrict__ tW1,
                                             const float* __restrict__ tb1,
                                             const float* __restrict__ tW2,
                                             const float* __restrict__ tb2,
                                             const float* __restrict__ eW1,
                                             const float* __restrict__ eb1,
                                             const float* __restrict__ eW2,
                                             const float* __restrict__ eb2,
                                             const float* __restrict__ eW3,
                                             const float* __restrict__ eb3,
                                             const float* __restrict__ gamma,
                                             const float* __restrict__ beta,
                                             float* __restrict__ out) {
    extern __shared__ char smem[];
    __nv_bfloat16* Xh = (__nv_bfloat16*)(smem + SM_XH);
    __nv_bfloat16* Xl = (__nv_bfloat16*)(smem + SM_XL);
    __nv_bfloat16* Wh = (__nv_bfloat16*)(smem + SM_WH);
    __nv_bfloat16* Wl = (__nv_bfloat16*)(smem + SM_WL);
    float*        red = (float*)(smem + SM_RED);          // [64][4]

    int t     = threadIdx.x;
    int wid   = t >> 5, lane = t & 31;
    int g     = lane >> 2;            // 0..7
    int la    = lane & 3;             // 0..3
    int wm    = wid >> 2;             // 0..1 : batch strip [wm*32, +32)
    int wn    = wid & 3;              // 0..3 : output strip [wn*16, +16)
    int b0    = blockIdx.x * MT;
    int oBase = blockIdx.y * NT;
    int unit  = blockIdx.z;

    // ---- stage X hi/lo (vectorized: float4 read -> 2x uint32 pair stores each half) ----
    if (unit < 3) {
        for (int i = t; i < MT * (KPAD / 4); i += 256) {
            int bb = i / (KPAD / 4), v4 = (i - bb * (KPAD / 4)) * 4;
            float x0 = 0.f, x1 = 0.f, x2 = 0.f, x3 = 0.f;
            if (v4 < NV) {
                float4 xv = *(const float4*)&g_udp[unit][b0 + bb][v4];
                float4 gm = *(const float4*)&gamma[v4];
                float4 mn = *(const float4*)&g_mean[unit][v4];
                float4 rs = *(const float4*)&g_rstd[unit][v4];
                float4 bt = *(const float4*)&beta[v4];
                x0 = gm.x * (xv.x - mn.x) * rs.x + bt.x;
                x1 = gm.y * (xv.y - mn.y) * rs.y + bt.y;
                x2 = gm.z * (xv.z - mn.z) * rs.z + bt.z;
                x3 = gm.w * (xv.w - mn.w) * rs.w + bt.w;
            }
            uint32_t h01, l01, h23, l23;
            split2(x0, x1, h01, l01);
            split2(x2, x3, h23, l23);
            int base = bb * XSTR + v4;          // even -> 4B aligned
            *(uint32_t*)&Xh[base]     = h01;
            *(uint32_t*)&Xh[base + 2] = h23;
            *(uint32_t*)&Xl[base]     = l01;
            *(uint32_t*)&Xl[base + 2] = l23;
        }
    } else {
        if (t < NV) {
            float w0 = eW1[t], w1 = eW1[NV + t], w2 = eW1[2 * NV + t], w3 = eW1[3 * NV + t];
            float bb1 = eb1[t];
            for (int bb = 0; bb < MT; bb++) {
                const float* mr = merged + (size_t)(b0 + bb) * NTOK * 15;
                float h = fmaxf(mr[3] * w0 + mr[4] * w1 + mr[5] * w2 + a[b0 + bb] * w3 + bb1, 0.f);
                __nv_bfloat16 hh = __float2bfloat16(h);
                Xh[bb * XSTR + t] = hh;
                Xl[bb * XSTR + t] = __float2bfloat16(h - __bfloat162float(hh));
            }
        }
        for (int i = t; i < MT * 8; i += 256) {
            int bb = i >> 3, v = NV + (i & 7);
            Xh[bb * XSTR + v] = __float2bfloat16(0.f);
            Xl[bb * XSTR + v] = __float2bfloat16(0.f);
        }
    }

    // ---- stage W^T hi/lo: Ws[o][k] = Wg[k][oBase+o] ----
    {
        const float* Wg = (unit < 3) ? tW1 + (size_t)unit * NV * NV : eW2;
        for (int i = t; i < KPAD * NT; i += 256) {
            int v = i / NT, o = i - v * NT;      // coalesced over o
            int oo = oBase + o;
            float wv = (v < NV && oo < NV) ? Wg[(size_t)v * NV + oo] : 0.f;
            __nv_bfloat16 h = __float2bfloat16(wv);
            Wh[o * XSTR + v] = h;
            Wl[o * XSTR + v] = __float2bfloat16(wv - __bfloat162float(h));
        }
    }
    __syncthreads();

    // ---- HMMA main loop: pass-reordered, split accumulators ----
    float chh[2][2][4], ccr[2][2][4];
#pragma unroll
    for (int mi = 0; mi < 2; mi++)
#pragma unroll
        for (int ni = 0; ni < 2; ni++)
#pragma unroll
            for (int j = 0; j < 4; j++) { chh[mi][ni][j] = 0.f; ccr[mi][ni][j] = 0.f; }

#pragma unroll
    for (int s = 0; s < NKS; s++) {
        int k0 = s * 16 + la * 2;
        uint32_t ah[2][4], al[2][4], bh[2][2], bl[2][2];
#pragma unroll
        for (int mi = 0; mi < 2; mi++) {
            int r = wm * 32 + mi * 16 + g;
            ah[mi][0] = *(const uint32_t*)&Xh[r * XSTR + k0];
            ah[mi][1] = *(const uint32_t*)&Xh[(r + 8) * XSTR + k0];
            ah[mi][2] = *(const uint32_t*)&Xh[r * XSTR + k0 + 8];
            ah[mi][3] = *(const uint32_t*)&Xh[(r + 8) * XSTR + k0 + 8];
            al[mi][0] = *(const uint32_t*)&Xl[r * XSTR + k0];
            al[mi][1] = *(const uint32_t*)&Xl[(r + 8) * XSTR + k0];
            al[mi][2] = *(const uint32_t*)&Xl[r * XSTR + k0 + 8];
            al[mi][3] = *(const uint32_t*)&Xl[(r + 8) * XSTR + k0 + 8];
        }
#pragma unroll
        for (int ni = 0; ni < 2; ni++) {
            int n = wn * 16 + ni * 8 + g;
            bh[ni][0] = *(const uint32_t*)&Wh[n * XSTR + k0];
            bh[ni][1] = *(const uint32_t*)&Wh[n * XSTR + k0 + 8];
            bl[ni][0] = *(const uint32_t*)&Wl[n * XSTR + k0];
            bl[ni][1] = *(const uint32_t*)&Wl[n * XSTR + k0 + 8];
        }
        // pass 1: hi*hi  (4 independent MMAs)
#pragma unroll
        for (int mi = 0; mi < 2; mi++)
#pragma unroll
            for (int ni = 0; ni < 2; ni++) mma16816(chh[mi][ni], ah[mi], bh[ni]);
        // pass 2+3: cross terms (8 independent MMAs into ccr)
#pragma unroll
        for (int mi = 0; mi < 2; mi++)
#pragma unroll
            for (int ni = 0; ni < 2; ni++) mma16816(ccr[mi][ni], ah[mi], bl[ni]);
#pragma unroll
        for (int mi = 0; mi < 2; mi++)
#pragma unroll
            for (int ni = 0; ni < 2; ni++) mma16816(ccr[mi][ni], al[mi], bh[ni]);
    }

    // ---- epilogue: bias + act + *W2, quad reduce, smem, atomicAdd ----
    const float* b1 = (unit < 3) ? tb1 + unit * NV : eb2;
    const float* w2 = (unit < 3) ? tW2 + unit * NV : eW3;

    float srow[2][2];   // [mi][half]
#pragma unroll
    for (int mi = 0; mi < 2; mi++) {
        srow[mi][0] = 0.f; srow[mi][1] = 0.f;
#pragma unroll
        for (int ni = 0; ni < 2; ni++) {
#pragma unroll
            for (int j = 0; j < 2; j++) {
                int oo = oBase + wn * 16 + ni * 8 + la * 2 + j;
                if (oo < NV) {
                    float bias = b1[oo], wv = w2[oo];
                    float v0 = chh[mi][ni][j]     + ccr[mi][ni][j]     + bias;   // row g
                    float v1 = chh[mi][ni][2 + j] + ccr[mi][ni][2 + j] + bias;   // row g+8
                    if (unit < 3) {
                        v0 = v0 > 0.f ? v0 : expm1f(v0);
                        v1 = v1 > 0.f ? v1 : expm1f(v1);
                    } else {
                        v0 = fmaxf(v0, 0.f);
                        v1 = fmaxf(v1, 0.f);
                    }
                    srow[mi][0] = fmaf(v0, wv, srow[mi][0]);
                    srow[mi][1] = fmaf(v1, wv, srow[mi][1]);
                }
            }
        }
#pragma unroll
        for (int off = 1; off <= 2; off <<= 1) {
            srow[mi][0] += __shfl_xor_sync(0xffffffffu, srow[mi][0], off);
            srow[mi][1] += __shfl_xor_sync(0xffffffffu, srow[mi][1], off);
        }
    }
    if (la == 0) {
#pragma unroll
        for (int mi = 0; mi < 2; mi++) {
            int r0 = wm * 32 + mi * 16 + g;
            red[r0 * 4 + wn]       = srow[mi][0];
            red[(r0 + 8) * 4 + wn] = srow[mi][1];
        }
    }
    __syncthreads();
    if (t < MT) {
        float s = red[t * 4 + 0] + red[t * 4 + 1] + red[t * 4 + 2] + red[t * 4 + 3];
        if (blockIdx.y == 0) s += (unit < 3) ? tb2[unit] : eb3[0];
        atomicAdd(&out[b0 + t], s);
    }
}

// ---------------- launch ----------------
extern "C" void kernel_launch(void* const* d_in, const int* in_sizes, int n_in,
                              void* d_out, int out_size) {
    (void)in_sizes; (void)n_in; (void)out_size;
    const float* merged = (const float*)d_in[0];
    const float* a      = (const float*)d_in[1];
    const float* upWq   = (const float*)d_in[2];
    const float* upWk   = (const float*)d_in[3];
    const float* upWv   = (const float*)d_in[4];
    const float* dnWq   = (const float*)d_in[5];
    const float* dnWk   = (const float*)d_in[6];
    const float* dnWv   = (const float*)d_in[7];
    const float* pvWq   = (const float*)d_in[8];
    const float* pvWk   = (const float*)d_in[9];
    const float* pvWv   = (const float*)d_in[10];
    const float* tW1    = (const float*)d_in[11];
    const float* tb1    = (const float*)d_in[12];
    const float* tW2    = (const float*)d_in[13];
    const float* tb2    = (const float*)d_in[14];
    const float* eW1    = (const float*)d_in[15];
    const float* eb1    = (const float*)d_in[16];
    const float* eW2    = (const float*)d_in[17];
    const float* eb2    = (const float*)d_in[18];
    const float* eW3    = (const float*)d_in[19];
    const float* eb3    = (const float*)d_in[20];
    const float* gamma  = (const float*)d_in[21];
    const float* beta   = (const float*)d_in[22];
    float* out = (float*)d_out;

    static bool attr_set = false;
    if (!attr_set) {
        cudaFuncSetAttribute(k_mlp, cudaFuncAttributeMaxDynamicSharedMemorySize, SM_TOT);
        attr_set = true;
    }

    k_pre<<<1, 256>>>(upWq, upWk, dnWq, dnWk, pvWq, pvWk);
    k_attn<<<NB, 256>>>(merged, a, upWv, dnWv, pvWv, out);
    k_stats<<<dim3(7, 3), dim3(32, 32)>>>();
    k_mlp<<<dim3(NB / MT, 4, 4), 256, SM_TOT>>>(merged, a, tW1, tb1, tW2, tb2,
                                                eW1, eb1, eW2, eb2, eW3, eb3,
                                                gamma, beta, out);
}

// round 15
// speedup vs baseline: 1.1446x; 1.0057x over previous
#include <cuda_runtime.h>
#include <cuda_bf16.h>
#include <math.h>
#include <stdint.h>

#define NB   1024
#define NTOK 256
#define NV   200

// ---- HMMA tile config ----
#define MT    64       // batches per block
#define NT    64       // outputs per block
#define KPAD  208      // padded K (13 x 16)
#define NKS   13
#define XSTR  216      // bf16 row stride: 432B = 27*16 -> ldmatrix 16B-aligned rows

// dynamic smem offsets (bytes)
#define SM_XH  0
#define SM_XL  (SM_XH + MT * XSTR * 2)        // 27,648 each
#define SM_WH  (SM_XL + MT * XSTR * 2)
#define SM_WL  (SM_WH + NT * XSTR * 2)
#define SM_RED (SM_WL + NT * XSTR * 2)
#define SM_TOT (SM_RED + MT * 4 * 4)          // 111,616 B -> 2 blocks/SM

// ---------------- device scratch ----------------
__device__ float g_M[245];            // Mu[7][14] | Md[7][14] | Mp[7][7]
__device__ float g_udp[3][NB][NV];
__device__ float g_mean[3][NV];
__device__ float g_rstd[3][NV];

// ---------------- helpers ----------------
__device__ __forceinline__ float warp_sum(float v) {
#pragma unroll
    for (int o = 16; o; o >>= 1) v += __shfl_xor_sync(0xffffffffu, v, o);
    return v;
}
__device__ __forceinline__ float warp_max(float v) {
#pragma unroll
    for (int o = 16; o; o >>= 1) v = fmaxf(v, __shfl_xor_sync(0xffffffffu, v, o));
    return v;
}
__device__ __forceinline__ void mma16816(float* c, const uint32_t* a, const uint32_t* b) {
    asm volatile(
        "mma.sync.aligned.m16n8k16.row.col.f32.bf16.bf16.f32 "
        "{%0,%1,%2,%3}, {%4,%5,%6,%7}, {%8,%9}, {%0,%1,%2,%3};"
        : "+f"(c[0]), "+f"(c[1]), "+f"(c[2]), "+f"(c[3])
        : "r"(a[0]), "r"(a[1]), "r"(a[2]), "r"(a[3]), "r"(b[0]), "r"(b[1]));
}
__device__ __forceinline__ void ldmx4(uint32_t* r, uint32_t addr) {
    asm volatile("ldmatrix.sync.aligned.m8n8.x4.shared.b16 {%0,%1,%2,%3}, [%4];"
        : "=r"(r[0]), "=r"(r[1]), "=r"(r[2]), "=r"(r[3]) : "r"(addr));
}
__device__ __forceinline__ uint32_t smem_u32(const void* p) {
    uint32_t a;
    asm("{ .reg .u64 t; cvta.to.shared.u64 t, %1; cvt.u32.u64 %0, t; }" : "=r"(a) : "l"(p));
    return a;
}
__device__ __forceinline__ uint32_t pack_bf16x2(float x, float y) {
    __nv_bfloat162 p = __floats2bfloat162_rn(x, y);
    return *(uint32_t*)&p;
}
__device__ __forceinline__ void split2(float x0, float x1, uint32_t& hi, uint32_t& lo) {
    __nv_bfloat16 h0 = __float2bfloat16(x0);
    __nv_bfloat16 h1 = __float2bfloat16(x1);
    float r0 = x0 - __bfloat162float(h0);
    float r1 = x1 - __bfloat162float(h1);
    __nv_bfloat162 hp; hp.x = h0; hp.y = h1;
    hi = *(uint32_t*)&hp;
    lo = pack_bf16x2(r0, r1);
}

// ---------------- kernel 0: M = Wq @ Wk^T (once) ----------------
__global__ void k_pre(const float* __restrict__ upWq, const float* __restrict__ upWk,
                      const float* __restrict__ dnWq, const float* __restrict__ dnWk,
                      const float* __restrict__ pvWq, const float* __restrict__ pvWk) {
    int t = threadIdx.x;
    if (t >= 245) return;
    const float *Wq, *Wk; int j, f;
    if (t < 98)       { Wq = upWq; Wk = upWk; j = t / 14;        f = t % 14; }
    else if (t < 196) { Wq = dnWq; Wk = dnWk; j = (t - 98) / 14; f = (t - 98) % 14; }
    else              { Wq = pvWq; Wk = pvWk; j = (t - 196) / 7; f = (t - 196) % 7; }
    const float4* q4 = (const float4*)(Wq + j * NV);
    const float4* k4 = (const float4*)(Wk + f * NV);
    float s = 0.f;
#pragma unroll 5
    for (int v = 0; v < NV / 4; v++) {
        float4 qa = q4[v], ka = k4[v];
        s += qa.x * ka.x + qa.y * ka.y + qa.z * ka.z + qa.w * ka.w;
    }
    g_M[t] = s;
}

// ---------------- kernel 1: attention, block-per-batch ----------------
__global__ __launch_bounds__(256) void k_attn(
    const float* __restrict__ merged, const float* __restrict__ a,
    const float* __restrict__ upWv, const float* __restrict__ dnWv,
    const float* __restrict__ pvWv, float* __restrict__ out)
{
    __shared__ float feat[NTOK * 15];
    __shared__ float sM[245];
    __shared__ float sqk[35];
    __shared__ float wred[8][6];
    __shared__ float wpart[8][38];
    __shared__ float sred[38];

    int b = blockIdx.x, t = threadIdx.x;
    int wid = t >> 5, lane = t & 31;

    const float4* src4 = (const float4*)(merged + (size_t)b * NTOK * 15);
    float4* feat4 = (float4*)feat;
#pragma unroll
    for (int i = 0; i < 4; i++) {
        int idx = t + 256 * i;
        if (idx < 960) feat4[idx] = src4[idx];
    }
    if (b < 4) out[b * 256 + t] = 0.f;
    if (t < 245) sM[t] = g_M[t];
    float a_b = a[b];
    __syncthreads();

    float subj_id = feat[0], subj_loc = feat[2];
    if (t < 35) {
        float ego[7];
        ego[0] = 0.f; ego[1] = feat[1]; ego[2] = feat[2]; ego[3] = feat[3];
        ego[4] = feat[4]; ego[5] = feat[5]; ego[6] = a_b;
        float s = 0.f;
        if (t < 14) {
#pragma unroll
            for (int j = 0; j < 7; j++) s += ego[j] * sM[j * 14 + t];
        } else if (t < 28) {
            int f = t - 14;
#pragma unroll
            for (int j = 0; j < 7; j++) s += ego[j] * sM[98 + j * 14 + f];
        } else {
            int f = t - 28;
#pragma unroll
            for (int j = 0; j < 7; j++) s += ego[j] * sM[196 + j * 7 + f];
        }
        sqk[t] = s;
    }
    __syncthreads();

    float f[15];
#pragma unroll
    for (int q = 0; q < 15; q++) f[q] = feat[t * 15 + q];
    f[0] -= subj_id; f[7] -= subj_id;
    if (t == 0) f[6] = a_b;

    float s1 = 0.f, s2 = 0.f, s3 = 0.f;
#pragma unroll
    for (int q = 0; q < 14; q++) { s1 = fmaf(f[q], sqk[q], s1); s2 = fmaf(f[q], sqk[14 + q], s2); }
#pragma unroll
    for (int q = 0; q < 7; q++)  s3 = fmaf(f[q], sqk[28 + q], s3);

    const float scale = 0.07071067811865475f;
    bool fl1  = (f[14] == 1.0f);
    bool m_up = (f[2] < subj_loc) && fl1;
    bool m_dn = (f[2] > subj_loc) && fl1;
    bool m_pv = (f[14] == 0.0f);
    float su = m_up ? s1 * scale : -1e9f;
    float sd = m_dn ? s2 * scale : -1e9f;
    float sp = m_pv ? s3 * scale : -1e9f;

    float mu = warp_max(su), md = warp_max(sd), mp = warp_max(sp);
    float cu = warp_sum(m_up ? 1.f : 0.f);
    float cd = warp_sum(m_dn ? 1.f : 0.f);
    float cp = warp_sum(m_pv ? 1.f : 0.f);
    if (lane == 0) {
        wred[wid][0] = mu; wred[wid][1] = md; wred[wid][2] = mp;
        wred[wid][3] = cu; wred[wid][4] = cd; wred[wid][5] = cp;
    }
    __syncthreads();
    float BU = wred[0][0], BD = wred[0][1], BP = wred[0][2];
    float CU = wred[0][3], CD = wred[0][4], CP = wred[0][5];
#pragma unroll
    for (int w = 1; w < 8; w++) {
        BU = fmaxf(BU, wred[w][0]); BD = fmaxf(BD, wred[w][1]); BP = fmaxf(BP, wred[w][2]);
        CU += wred[w][3]; CD += wred[w][4]; CP += wred[w][5];
    }
    float eu = __expf(su - BU), ed = __expf(sd - BD), ep = __expf(sp - BP);

    float vals[38];
    vals[0] = eu; vals[1] = ed; vals[2] = ep;
#pragma unroll
    for (int q = 0; q < 14; q++) { vals[3 + q] = eu * f[q]; vals[17 + q] = ed * f[q]; }
#pragma unroll
    for (int q = 0; q < 7; q++)  vals[31 + q] = ep * f[q];
#pragma unroll
    for (int i = 0; i < 38; i++) {
        float v = warp_sum(vals[i]);
        if (lane == 0) wpart[wid][i] = v;
    }
    __syncthreads();
    if (t < 38) {
        float s = 0.f;
#pragma unroll
        for (int w = 0; w < 8; w++) s += wpart[w][t];
        sred[t] = s;
    }
    __syncthreads();

    if (t < NV) {
        float iSu = (CU > 0.5f) ? 1.f / sred[0] : 0.f;
        float iSd = (CD > 0.5f) ? 1.f / sred[1] : 0.f;
        float iSp = (CP > 0.5f) ? 1.f / sred[2] : 0.f;
        float ou = 0.f, od = 0.f, op = 0.f;
#pragma unroll
        for (int q = 0; q < 14; q++) {
            ou = fmaf(sred[3 + q],  __ldg(&upWv[q * NV + t]), ou);
            od = fmaf(sred[17 + q], __ldg(&dnWv[q * NV + t]), od);
        }
#pragma unroll
        for (int q = 0; q < 7; q++)
            op = fmaf(sred[31 + q], __ldg(&pvWv[q * NV + t]), op);
        g_udp[0][b][t] = ou * iSu;
        g_udp[1][b][t] = od * iSd;
        g_udp[2][b][t] = op * iSp;
    }
}

// ---------------- kernel 2: batch-norm stats (fp32, tree reduce) ----------------
__global__ void k_stats() {
    int k  = blockIdx.y;
    int vx = threadIdx.x;
    int by = threadIdx.y;
    int v  = blockIdx.x * 32 + vx;
    float s = 0.f, s2 = 0.f;
    if (v < NV) {
#pragma unroll 4
        for (int j = 0; j < 32; j++) {
            float x = g_udp[k][by + 32 * j][v];
            s += x;
            s2 = fmaf(x, x, s2);
        }
    }
    __shared__ float ss[32][33], ss2[32][33];
    ss[by][vx]  = s;
    ss2[by][vx] = s2;
    __syncthreads();
#pragma unroll
    for (int off = 16; off; off >>= 1) {
        if (by < off) {
            ss[by][vx]  += ss[by + off][vx];
            ss2[by][vx] += ss2[by + off][vx];
        }
        __syncthreads();
    }
    if (by == 0 && v < NV) {
        float mean = ss[0][vx] * (1.f / NB);
        float var  = ss2[0][vx] * (1.f / NB) - mean * mean;
        g_mean[k][v] = mean;
        g_rstd[k][v] = rsqrtf(var + 1e-5f);
    }
}

// ---------------- kernel 3: HMMA bf16 split GEMM, ldmatrix fragments ----------------
// Block = 64 batches x 64 outputs x full K. grid (16, 4, 4) = 256 blocks, 2/SM.
// 8 warps: wm = wid>>2 (2 M strips of 32), wn = wid&3 (4 N strips of 16).
// Per k-step: 6 ldmatrix.x4 + 12 HMMA (pass-reordered, split accumulators).
__global__ __launch_bounds__(256) void k_mlp(const float* __restrict__ merged,
                                             const float* __restrict__ a,
                                             const float* __restrict__ tW1,
                                             const float* __restrict__ tb1,
                                             const float* __restrict__ tW2,
                                             const float* __restrict__ tb2,
                                             const float* __restrict__ eW1,
                                             const float* __restrict__ eb1,
                                             const float* __restrict__ eW2,
                                             const float* __restrict__ eb2,
                                             const float* __restrict__ eW3,
                                             const float* __restrict__ eb3,
                                             const float* __restrict__ gamma,
                                             const float* __restrict__ beta,
                                             float* __restrict__ out) {
    extern __shared__ char smem[];
    __nv_bfloat16* Xh = (__nv_bfloat16*)(smem + SM_XH);
    __nv_bfloat16* Xl = (__nv_bfloat16*)(smem + SM_XL);
    __nv_bfloat16* Wh = (__nv_bfloat16*)(smem + SM_WH);
    __nv_bfloat16* Wl = (__nv_bfloat16*)(smem + SM_WL);
    float*        red = (float*)(smem + SM_RED);          // [64][4]

    int t     = threadIdx.x;
    int wid   = t >> 5, lane = t & 31;
    int g     = lane >> 2;            // 0..7
    int la    = lane & 3;             // 0..3
    int wm    = wid >> 2;             // 0..1 : batch strip [wm*32, +32)
    int wn    = wid & 3;              // 0..3 : output strip [wn*16, +16)
    int b0    = blockIdx.x * MT;
    int oBase = blockIdx.y * NT;
    int unit  = blockIdx.z;

    // ---- stage X hi/lo ----
    if (unit < 3) {
        for (int i = t; i < MT * (KPAD / 4); i += 256) {
            int bb = i / (KPAD / 4), v4 = (i - bb * (KPAD / 4)) * 4;
            float x0 = 0.f, x1 = 0.f, x2 = 0.f, x3 = 0.f;
            if (v4 < NV) {
                float4 xv = *(const float4*)&g_udp[unit][b0 + bb][v4];
                float4 gm = *(const float4*)&gamma[v4];
                float4 mn = *(const float4*)&g_mean[unit][v4];
                float4 rs = *(const float4*)&g_rstd[unit][v4];
                float4 bt = *(const float4*)&beta[v4];
                x0 = gm.x * (xv.x - mn.x) * rs.x + bt.x;
                x1 = gm.y * (xv.y - mn.y) * rs.y + bt.y;
                x2 = gm.z * (xv.z - mn.z) * rs.z + bt.z;
                x3 = gm.w * (xv.w - mn.w) * rs.w + bt.w;
            }
            uint32_t h01, l01, h23, l23;
            split2(x0, x1, h01, l01);
            split2(x2, x3, h23, l23);
            int base = bb * XSTR + v4;          // even -> 4B aligned
            *(uint32_t*)&Xh[base]     = h01;
            *(uint32_t*)&Xh[base + 2] = h23;
            *(uint32_t*)&Xl[base]     = l01;
            *(uint32_t*)&Xl[base + 2] = l23;
        }
    } else {
        if (t < NV) {
            float w0 = eW1[t], w1 = eW1[NV + t], w2 = eW1[2 * NV + t], w3 = eW1[3 * NV + t];
            float bb1 = eb1[t];
            for (int bb = 0; bb < MT; bb++) {
                const float* mr = merged + (size_t)(b0 + bb) * NTOK * 15;
                float h = fmaxf(mr[3] * w0 + mr[4] * w1 + mr[5] * w2 + a[b0 + bb] * w3 + bb1, 0.f);
                __nv_bfloat16 hh = __float2bfloat16(h);
                Xh[bb * XSTR + t] = hh;
                Xl[bb * XSTR + t] = __float2bfloat16(h - __bfloat162float(hh));
            }
        }
        for (int i = t; i < MT * 8; i += 256) {
            int bb = i >> 3, v = NV + (i & 7);
            Xh[bb * XSTR + v] = __float2bfloat16(0.f);
            Xl[bb * XSTR + v] = __float2bfloat16(0.f);
        }
    }

    // ---- stage W^T hi/lo: Ws[o][k] = Wg[k][oBase+o] ----
    {
        const float* Wg = (unit < 3) ? tW1 + (size_t)unit * NV * NV : eW2;
        for (int i = t; i < KPAD * NT; i += 256) {
            int v = i / NT, o = i - v * NT;      // coalesced over o
            int oo = oBase + o;
            float wv = (v < NV && oo < NV) ? Wg[(size_t)v * NV + oo] : 0.f;
            __nv_bfloat16 h = __float2bfloat16(wv);
            Wh[o * XSTR + v] = h;
            Wl[o * XSTR + v] = __float2bfloat16(wv - __bfloat162float(h));
        }
    }
    __syncthreads();

    // ---- precompute ldmatrix lane addresses (byte offsets advance 32B per k-step) ----
    int lrow  = (lane & 15);          // row within 16-row tile (mats 0,1)
    int khalf = (lane >> 4) & 1;      // k0 (+0) or k0+8 (mats 2,3)
    uint32_t aXh0 = smem_u32(&Xh[(wm * 32 + lrow) * XSTR + khalf * 8]);
    uint32_t aXh1 = smem_u32(&Xh[(wm * 32 + 16 + lrow) * XSTR + khalf * 8]);
    uint32_t aXl0 = smem_u32(&Xl[(wm * 32 + lrow) * XSTR + khalf * 8]);
    uint32_t aXl1 = smem_u32(&Xl[(wm * 32 + 16 + lrow) * XSTR + khalf * 8]);
    uint32_t aWh  = smem_u32(&Wh[(wn * 16 + lrow) * XSTR + khalf * 8]);
    uint32_t aWl  = smem_u32(&Wl[(wn * 16 + lrow) * XSTR + khalf * 8]);

    // ---- HMMA main loop ----
    float chh[2][2][4], ccr[2][2][4];
#pragma unroll
    for (int mi = 0; mi < 2; mi++)
#pragma unroll
        for (int ni = 0; ni < 2; ni++)
#pragma unroll
            for (int j = 0; j < 4; j++) { chh[mi][ni][j] = 0.f; ccr[mi][ni][j] = 0.f; }

#pragma unroll
    for (int s = 0; s < NKS; s++) {
        uint32_t koff = (uint32_t)s * 32;     // 16 bf16 = 32 bytes
        uint32_t ah[2][4], al[2][4], wh[4], wl[4];
        ldmx4(ah[0], aXh0 + koff);
        ldmx4(ah[1], aXh1 + koff);
        ldmx4(al[0], aXl0 + koff);
        ldmx4(al[1], aXl1 + koff);
        ldmx4(wh, aWh + koff);                // wh = {b[0][0], b[1][0], b[0][1], b[1][1]}
        ldmx4(wl, aWl + koff);
        uint32_t bh0[2] = {wh[0], wh[2]}, bh1[2] = {wh[1], wh[3]};
        uint32_t bl0[2] = {wl[0], wl[2]}, bl1[2] = {wl[1], wl[3]};
        // pass 1: hi*hi
        mma16816(chh[0][0], ah[0], bh0); mma16816(chh[0][1], ah[0], bh1);
        mma16816(chh[1][0], ah[1], bh0); mma16816(chh[1][1], ah[1], bh1);
        // pass 2: hi*lo
        mma16816(ccr[0][0], ah[0], bl0); mma16816(ccr[0][1], ah[0], bl1);
        mma16816(ccr[1][0], ah[1], bl0); mma16816(ccr[1][1], ah[1], bl1);
        // pass 3: lo*hi
        mma16816(ccr[0][0], al[0], bh0); mma16816(ccr[0][1], al[0], bh1);
        mma16816(ccr[1][0], al[1], bh0); mma16816(ccr[1][1], al[1], bh1);
    }

    // ---- epilogue: bias + act + *W2, quad reduce, smem, atomicAdd ----
    const float* b1 = (unit < 3) ? tb1 + unit * NV : eb2;
    const float* w2 = (unit < 3) ? tW2 + unit * NV : eW3;

    float srow[2][2];   // [mi][half]
#pragma unroll
    for (int mi = 0; mi < 2; mi++) {
        srow[mi][0] = 0.f; srow[mi][1] = 0.f;
#pragma unroll
        for (int ni = 0; ni < 2; ni++) {
#pragma unroll
            for (int j = 0; j < 2; j++) {
                int oo = oBase + wn * 16 + ni * 8 + la * 2 + j;
                if (oo < NV) {
                    float bias = b1[oo], wv = w2[oo];
                    float v0 = chh[mi][ni][j]     + ccr[mi][ni][j]     + bias;   // row g
                    float v1 = chh[mi][ni][2 + j] + ccr[mi][ni][2 + j] + bias;   // row g+8
                    if (unit < 3) {
                        v0 = v0 > 0.f ? v0 : expm1f(v0);
                        v1 = v1 > 0.f ? v1 : expm1f(v1);
                    } else {
                        v0 = fmaxf(v0, 0.f);
                        v1 = fmaxf(v1, 0.f);
                    }
                    srow[mi][0] = fmaf(v0, wv, srow[mi][0]);
                    srow[mi][1] = fmaf(v1, wv, srow[mi][1]);
                }
            }
        }
#pragma unroll
        for (int off = 1; off <= 2; off <<= 1) {
            srow[mi][0] += __shfl_xor_sync(0xffffffffu, srow[mi][0], off);
            srow[mi][1] += __shfl_xor_sync(0xffffffffu, srow[mi][1], off);
        }
    }
    if (la == 0) {
#pragma unroll
        for (int mi = 0; mi < 2; mi++) {
            int r0 = wm * 32 + mi * 16 + g;
            red[r0 * 4 + wn]       = srow[mi][0];
            red[(r0 + 8) * 4 + wn] = srow[mi][1];
        }
    }
    __syncthreads();
    if (t < MT) {
        float s = red[t * 4 + 0] + red[t * 4 + 1] + red[t * 4 + 2] + red[t * 4 + 3];
        if (blockIdx.y == 0) s += (unit < 3) ? tb2[unit] : eb3[0];
        atomicAdd(&out[b0 + t], s);
    }
}

// ---------------- launch ----------------
extern "C" void kernel_launch(void* const* d_in, const int* in_sizes, int n_in,
                              void* d_out, int out_size) {
    (void)in_sizes; (void)n_in; (void)out_size;
    const float* merged = (const float*)d_in[0];
    const float* a      = (const float*)d_in[1];
    const float* upWq   = (const float*)d_in[2];
    const float* upWk   = (const float*)d_in[3];
    const float* upWv   = (const float*)d_in[4];
    const float* dnWq   = (const float*)d_in[5];
    const float* dnWk   = (const float*)d_in[6];
    const float* dnWv   = (const float*)d_in[7];
    const float* pvWq   = (const float*)d_in[8];
    const float* pvWk   = (const float*)d_in[9];
    const float* pvWv   = (const float*)d_in[10];
    const float* tW1    = (const float*)d_in[11];
    const float* tb1    = (const float*)d_in[12];
    const float* tW2    = (const float*)d_in[13];
    const float* tb2    = (const float*)d_in[14];
    const float* eW1    = (const float*)d_in[15];
    const float* eb1    = (const float*)d_in[16];
    const float* eW2    = (const float*)d_in[17];
    const float* eb2    = (const float*)d_in[18];
    const float* eW3    = (const float*)d_in[19];
    const float* eb3    = (const float*)d_in[20];
    const float* gamma  = (const float*)d_in[21];
    const float* beta   = (const float*)d_in[22];
    float* out = (float*)d_out;

    static bool attr_set = false;
    if (!attr_set) {
        cudaFuncSetAttribute(k_mlp, cudaFuncAttributeMaxDynamicSharedMemorySize, SM_TOT);
        attr_set = true;
    }

    k_pre<<<1, 256>>>(upWq, upWk, dnWq, dnWk, pvWq, pvWk);
    k_attn<<<NB, 256>>>(merged, a, upWv, dnWv, pvWv, out);
    k_stats<<<dim3(7, 3), dim3(32, 32)>>>();
    k_mlp<<<dim3(NB / MT, 4, 4), 256, SM_TOT>>>(merged, a, tW1, tb1, tW2, tb2,
                                                eW1, eb1, eW2, eb2, eW3, eb3,
                                                gamma, beta, out);
}